// round 16
// baseline (speedup 1.0000x reference)
#include <cuda_runtime.h>
#include <cstdint>

// y2[a,d,z] = sum_c ( sum_b x1[a,b,z]*x0[b,c,z] ) * x2[c,d,z]
// All tensors (32,32,32768) fp32 row-major, z contiguous. Lane = one f32x2 z-pair.
// R16: occupancy experiment. R14 structure (8a x 8c warp tile, rotated
// reduction order, y1 64KB smem, 128-thr/4-warp blocks) but THREE blocks/SM
// (12 warps = 3/SMSP). Reg cap 170 forces bv/xv to load-at-use (no register
// double-buffer); the third warp per scheduler replaces the buffer as the
// latency-hiding mechanism. Rotation keeps the streams decorrelated and
// makes follower bv/xv loads L2 hits.

#define ZH   16384          // z-pairs (f32x2)
#define SDIM 32

using u64 = unsigned long long;

__device__ __forceinline__ u64 ffma2(u64 a, u64 b, u64 c) {
    u64 d;
    asm("fma.rn.f32x2 %0, %1, %2, %3;" : "=l"(d) : "l"(a), "l"(b), "l"(c));
    return d;
}

__global__ void __launch_bounds__(128, 3)
einnet_fused12_kernel(const u64* __restrict__ x0,
                      const u64* __restrict__ x1,
                      const u64* __restrict__ x2,
                      u64* __restrict__ out)
{
    // y1 tile: [a(8)][c(32)][lane(32)] u64 = 64KB
    extern __shared__ u64 y1s[];

    const int lane = threadIdx.x & 31;
    const int w    = threadIdx.x >> 5;            // 0..3
    const int cg   = w * 8;                       // c/d stripe base (output cols)
    const int abas = blockIdx.x * 8;              // a-group base (0,8,16,24)
    const int p    = blockIdx.y * 32 + lane;      // global z-pair
    const int rot  = (w + blockIdx.x) & 3;        // reduction-order rotation

    u64 acc[8][8];
    #pragma unroll
    for (int i = 0; i < 8; i++)
        #pragma unroll
        for (int j = 0; j < 8; j++) acc[i][j] = 0ull;

    // ---------------- Pass 1: y1[a,c] = sum_b x1[a,b] * x0[b,c] ----------------
    const u64* __restrict__ Ap = x1 + (size_t)(abas * SDIM) * ZH + p;
    const u64* __restrict__ Bp = x0 + (size_t)cg * ZH + p;

    for (int kk = 0; kk < 4; kk++) {              // 4 chunks (runtime rot base)
        const int ch = (rot + kk) & 3;
        const u64* __restrict__ Ar = Ap + (size_t)(ch * 8) * ZH;         // av rows
        const u64* __restrict__ Br = Bp + (size_t)(ch * 8) * SDIM * ZH;  // bv rows

        #pragma unroll
        for (int s = 0; s < 8; s++) {             // compile-time steps
            u64 bv[8], av[8];
            #pragma unroll
            for (int j = 0; j < 8; j++) bv[j] = Br[(size_t)(s * SDIM + j) * ZH];
            #pragma unroll
            for (int i = 0; i < 8; i++) av[i] = Ar[(size_t)(i * SDIM + s) * ZH];

            #pragma unroll
            for (int i = 0; i < 8; i++)
                #pragma unroll
                for (int j = 0; j < 8; j++)
                    acc[i][j] = ffma2(av[i], bv[j], acc[i][j]);
        }
    }

    // store y1 stripe (conflict-free: lane-consecutive 8B)
    #pragma unroll
    for (int i = 0; i < 8; i++)
        #pragma unroll
        for (int j = 0; j < 8; j++)
            y1s[(i * SDIM + cg + j) * 32 + lane] = acc[i][j];
    __syncthreads();

    // ---------------- Pass 2: y2[a,d] = sum_c y1[a,c] * x2[c,d] ----------------
    #pragma unroll
    for (int i = 0; i < 8; i++)
        #pragma unroll
        for (int j = 0; j < 8; j++) acc[i][j] = 0ull;

    const u64* __restrict__ Cp = x2 + (size_t)cg * ZH + p;

    for (int kk = 0; kk < 4; kk++) {
        const int ch = (rot + kk) & 3;
        const u64* __restrict__ Cr = Cp + (size_t)(ch * 8) * SDIM * ZH;
        const u64* __restrict__ Yr = y1s + (size_t)(ch * 8) * 32;   // y1 rows (c dim)

        #pragma unroll
        for (int s = 0; s < 8; s++) {
            u64 xv[8], yv[8];
            #pragma unroll
            for (int j = 0; j < 8; j++) xv[j] = Cr[(size_t)(s * SDIM + j) * ZH];
            #pragma unroll
            for (int i = 0; i < 8; i++)
                yv[i] = Yr[((size_t)i * SDIM + s) * 32 + lane];   // smem, conflict-free

            #pragma unroll
            for (int i = 0; i < 8; i++)
                #pragma unroll
                for (int j = 0; j < 8; j++)
                    acc[i][j] = ffma2(yv[i], xv[j], acc[i][j]);
        }
    }

    u64* __restrict__ Op = out + (size_t)(abas * SDIM + cg) * ZH + p;
    #pragma unroll
    for (int i = 0; i < 8; i++)
        #pragma unroll
        for (int j = 0; j < 8; j++)
            Op[(size_t)(i * SDIM + j) * ZH] = acc[i][j];
}

extern "C" void kernel_launch(void* const* d_in, const int* in_sizes, int n_in,
                              void* d_out, int out_size)
{
    (void)in_sizes; (void)n_in; (void)out_size;
    const u64* x0 = (const u64*)d_in[0];   // (b, c, Z)
    const u64* x1 = (const u64*)d_in[1];   // (a, b, Z)
    const u64* x2 = (const u64*)d_in[2];   // (c, d, Z)
    u64* out = (u64*)d_out;

    constexpr int SMEM_BYTES = 8 * SDIM * 32 * 8;   // 65536 = 64KB
    cudaFuncSetAttribute(einnet_fused12_kernel,
                         cudaFuncAttributeMaxDynamicSharedMemorySize, SMEM_BYTES);

    // z-tile slow dim: the 4 a-group blocks of one z-tile are co-resident
    // (3 per SM) and share x0/x2 slices in L2.
    dim3 grid(4, ZH / 32);
    einnet_fused12_kernel<<<grid, 128, SMEM_BYTES>>>(x0, x1, x2, out);
}

// round 17
// speedup vs baseline: 1.4817x; 1.4817x over previous
#include <cuda_runtime.h>
#include <cstdint>

// y2[a,d,z] = sum_c ( sum_b x1[a,b,z]*x0[b,c,z] ) * x2[c,d,z]
// All tensors (32,32,32768) fp32 row-major, z contiguous. Lane = one f32x2 z-pair.
// R17 = R14 base (128thr/4 warps, 8a x 8c tile, y1 64KB smem, 2 blocks/SM,
// distance-1 reg double-buffer on bv/xv, chunk-rotated reduction order)
// + NEW: av (x1) staged through smem via per-CHUNK cp.async double buffer.
// av is block-uniform (all 4 warps previously LDG'd identical addresses at
// distance 0 -> one exposed DRAM miss convoy per step). Now: one cp.async
// fill per 8-step chunk (16KB, ~2000cyc lead, 2 barriers/chunk), consumed as
// conflict-free LDS. Rotation is block-uniform (preserves cross-block bv/xv
// L2 sharing decorrelation; intra-block av correlation is moot with staging).

#define ZH   16384          // z-pairs (f32x2)
#define SDIM 32

using u64 = unsigned long long;

__device__ __forceinline__ u64 ffma2(u64 a, u64 b, u64 c) {
    u64 d;
    asm("fma.rn.f32x2 %0, %1, %2, %3;" : "=l"(d) : "l"(a), "l"(b), "l"(c));
    return d;
}

__device__ __forceinline__ void cp16(u64* dst, const u64* src) {
    unsigned d = (unsigned)__cvta_generic_to_shared(dst);
    asm volatile("cp.async.cg.shared.global [%0], [%1], 16;"
                 :: "r"(d), "l"(src) : "memory");
}
__device__ __forceinline__ void cp_commit() {
    asm volatile("cp.async.commit_group;" ::: "memory");
}
__device__ __forceinline__ void cp_wait1() {
    asm volatile("cp.async.wait_group 1;" ::: "memory");
}

// Fill one av chunk: 8 a-rows x 8 b-steps x 32 z-pairs = 2048 u64 = 16KB.
// dst layout [r = i*8+s][lane]; src row (i,s) at base + i*32*ZH + s*ZH.
// 1024 16B chunks / 128 threads = 8 per thread.
__device__ __forceinline__ void fill_av(u64* dst, const u64* base, int tid) {
    #pragma unroll
    for (int k = 0; k < 8; k++) {
        int q = tid + k * 128;
        int r = q >> 4;                 // 0..63
        int m = q & 15;                 // 16B chunk within 256B row
        cp16(dst + r * 32 + 2 * m,
             base + (size_t)(r >> 3) * (32 * ZH) + (size_t)(r & 7) * ZH + 2 * m);
    }
}

__global__ void __launch_bounds__(128, 2)
einnet_fused13_kernel(const u64* __restrict__ x0,
                      const u64* __restrict__ x1,
                      const u64* __restrict__ x2,
                      u64* __restrict__ out)
{
    extern __shared__ u64 smem[];
    u64* avs = smem;            // 2 x 2048 u64 = 32KB av stage
    u64* y1s = smem + 4096;     // 8192 u64 = 64KB y1 tile

    const int tid  = threadIdx.x;
    const int lane = tid & 31;
    const int w    = tid >> 5;                    // 0..3
    const int cg   = w * 8;                       // c/d stripe base (output cols)
    const int abas = blockIdx.x * 8;              // a-group base (0,8,16,24)
    const int zb   = blockIdx.y * 32;
    const int p    = zb + lane;                   // global z-pair
    const int rot  = blockIdx.x & 3;              // block-uniform rotation

    u64 acc[8][8];
    #pragma unroll
    for (int i = 0; i < 8; i++)
        #pragma unroll
        for (int j = 0; j < 8; j++) acc[i][j] = 0ull;

    // ---------------- Pass 1: y1[a,c] = sum_b x1[a,b] * x0[b,c] ----------------
    const u64* __restrict__ A0 = x1 + (size_t)(abas * SDIM) * ZH + zb;  // chunk base w/o ch
    const u64* __restrict__ Bp = x0 + (size_t)cg * ZH + p;

    // prologue: fill chunk rot into buf 0
    fill_av(avs, A0 + (size_t)(rot * 8) * ZH, tid);
    cp_commit();

    u64 bv[2][8];
    {   // initial bv load: chunk rot, step 0
        const u64* Br = Bp + (size_t)(rot * 8) * SDIM * ZH;
        #pragma unroll
        for (int j = 0; j < 8; j++) bv[0][j] = Br[(size_t)j * ZH];
    }

    for (int kk = 0; kk < 4; kk++) {
        const int ch  = (rot + kk) & 3;
        const int chn = (rot + kk + 1) & 3;
        const u64* __restrict__ Br  = Bp + (size_t)(ch  * 8) * SDIM * ZH;
        const u64* __restrict__ Brn = Bp + (size_t)(chn * 8) * SDIM * ZH;
        u64* __restrict__ Ab = avs + (kk & 1) * 2048;        // this chunk's buffer

        __syncthreads();            // everyone finished consuming chunk kk-1
        if (kk + 1 < 4)
            fill_av(avs + ((kk + 1) & 1) * 2048, A0 + (size_t)(chn * 8) * ZH, tid);
        cp_commit();                // unconditional: uniform group ledger
        cp_wait1();                 // chunk kk's fill drained (my portion)
        __syncthreads();            // everyone's portion landed

        #pragma unroll
        for (int s = 0; s < 8; s++) {
            const int cur = s & 1;
            if (s + 1 < 8) {
                #pragma unroll
                for (int j = 0; j < 8; j++)
                    bv[cur ^ 1][j] = Br[(size_t)((s + 1) * SDIM + j) * ZH];
            } else if (kk + 1 < 4) {
                #pragma unroll
                for (int j = 0; j < 8; j++)
                    bv[cur ^ 1][j] = Brn[(size_t)j * ZH];
            }

            u64 av[8];
            #pragma unroll
            for (int i = 0; i < 8; i++)
                av[i] = Ab[(i * 8 + s) * 32 + lane];     // conflict-free LDS

            #pragma unroll
            for (int i = 0; i < 8; i++)
                #pragma unroll
                for (int j = 0; j < 8; j++)
                    acc[i][j] = ffma2(av[i], bv[cur][j], acc[i][j]);
        }
    }

    // store y1 stripe (conflict-free: lane-consecutive 8B)
    #pragma unroll
    for (int i = 0; i < 8; i++)
        #pragma unroll
        for (int j = 0; j < 8; j++)
            y1s[(i * SDIM + cg + j) * 32 + lane] = acc[i][j];
    __syncthreads();

    // ---------------- Pass 2: y2[a,d] = sum_c y1[a,c] * x2[c,d] ----------------
    #pragma unroll
    for (int i = 0; i < 8; i++)
        #pragma unroll
        for (int j = 0; j < 8; j++) acc[i][j] = 0ull;

    const u64* __restrict__ Cp = x2 + (size_t)cg * ZH + p;

    u64 xv[2][8];
    {
        const u64* Cr = Cp + (size_t)(rot * 8) * SDIM * ZH;
        #pragma unroll
        for (int j = 0; j < 8; j++) xv[0][j] = Cr[(size_t)j * ZH];
    }

    for (int kk = 0; kk < 4; kk++) {
        const int ch  = (rot + kk) & 3;
        const int chn = (rot + kk + 1) & 3;
        const u64* __restrict__ Cr  = Cp + (size_t)(ch  * 8) * SDIM * ZH;
        const u64* __restrict__ Crn = Cp + (size_t)(chn * 8) * SDIM * ZH;
        const u64* __restrict__ Yr  = y1s + (size_t)(ch * 8) * 32;

        #pragma unroll
        for (int s = 0; s < 8; s++) {
            const int cur = s & 1;
            if (s + 1 < 8) {
                #pragma unroll
                for (int j = 0; j < 8; j++)
                    xv[cur ^ 1][j] = Cr[(size_t)((s + 1) * SDIM + j) * ZH];
            } else if (kk + 1 < 4) {
                #pragma unroll
                for (int j = 0; j < 8; j++)
                    xv[cur ^ 1][j] = Crn[(size_t)j * ZH];
            }

            u64 yv[8];
            #pragma unroll
            for (int i = 0; i < 8; i++)
                yv[i] = Yr[((size_t)i * SDIM + s) * 32 + lane];   // smem, conflict-free

            #pragma unroll
            for (int i = 0; i < 8; i++)
                #pragma unroll
                for (int j = 0; j < 8; j++)
                    acc[i][j] = ffma2(yv[i], xv[cur][j], acc[i][j]);
        }
    }

    u64* __restrict__ Op = out + (size_t)(abas * SDIM + cg) * ZH + p;
    #pragma unroll
    for (int i = 0; i < 8; i++)
        #pragma unroll
        for (int j = 0; j < 8; j++)
            Op[(size_t)(i * SDIM + j) * ZH] = acc[i][j];
}

extern "C" void kernel_launch(void* const* d_in, const int* in_sizes, int n_in,
                              void* d_out, int out_size)
{
    (void)in_sizes; (void)n_in; (void)out_size;
    const u64* x0 = (const u64*)d_in[0];   // (b, c, Z)
    const u64* x1 = (const u64*)d_in[1];   // (a, b, Z)
    const u64* x2 = (const u64*)d_in[2];   // (c, d, Z)
    u64* out = (u64*)d_out;

    constexpr int SMEM_BYTES = (4096 + 8192) * 8;   // 96KB
    cudaFuncSetAttribute(einnet_fused13_kernel,
                         cudaFuncAttributeMaxDynamicSharedMemorySize, SMEM_BYTES);

    // z-tile slow dim: the 4 a-group blocks of one z-tile are co-resident
    // (2 per SM) and share x0/x2 slices in L2.
    dim3 grid(4, ZH / 32);
    einnet_fused13_kernel<<<grid, 128, SMEM_BYTES>>>(x0, x1, x2, out);
}